// round 5
// baseline (speedup 1.0000x reference)
#include <cuda_runtime.h>
#include <cstdint>
#include <math.h>

// Problem constants
#define BB   64
#define TT   128
#define EE   256
#define HH   256
#define BT   (BB*TT)        // 8192

// Scratch: input-drive buffer xp[B*T, HH] (8 MB) for level 0 only.
__device__ float g_xp[BT * HH];

// ---------------------------------------------------------------------------
// GEMM: g_xp[m, n] = sum_k A[row(m), k] * W[n, k] + bias[n]
// ---------------------------------------------------------------------------
__global__ __launch_bounds__(256) void gemm_xp(
    const float* __restrict__ A, const int* __restrict__ rowidx, int astride,
    const float* __restrict__ W, const float* __restrict__ bias)
{
    __shared__ float As[32][68];
    __shared__ float Bs[32][68];

    const int m0  = blockIdx.x * 64;
    const int n0  = blockIdx.y * 64;
    const int tid = threadIdx.x;
    const int lr  = tid >> 3;
    const int lk  = (tid & 7) << 2;
    const int ty  = tid >> 4;
    const int tx  = tid & 15;

    float acc[4][4] = {};

    for (int k0 = 0; k0 < 256; k0 += 32) {
        #pragma unroll
        for (int rr = 0; rr < 2; rr++) {
            int m  = m0 + lr + rr * 32;
            int ar = rowidx ? rowidx[m] : m;
            float4 a4 = *(const float4*)(A + (size_t)ar * astride + k0 + lk);
            As[lk + 0][lr + rr * 32] = a4.x;
            As[lk + 1][lr + rr * 32] = a4.y;
            As[lk + 2][lr + rr * 32] = a4.z;
            As[lk + 3][lr + rr * 32] = a4.w;

            int n = n0 + lr + rr * 32;
            float4 b4 = *(const float4*)(W + (size_t)n * 256 + k0 + lk);
            Bs[lk + 0][lr + rr * 32] = b4.x;
            Bs[lk + 1][lr + rr * 32] = b4.y;
            Bs[lk + 2][lr + rr * 32] = b4.z;
            Bs[lk + 3][lr + rr * 32] = b4.w;
        }
        __syncthreads();

        #pragma unroll
        for (int kk = 0; kk < 32; kk++) {
            float a[4], b[4];
            *(float4*)a = *(const float4*)&As[kk][ty << 2];
            *(float4*)b = *(const float4*)&Bs[kk][tx << 2];
            #pragma unroll
            for (int i = 0; i < 4; i++)
                #pragma unroll
                for (int jx = 0; jx < 4; jx++)
                    acc[i][jx] = fmaf(a[i], b[jx], acc[i][jx]);
        }
        __syncthreads();
    }

    float4 bv = *(const float4*)(bias + n0 + (tx << 2));
    #pragma unroll
    for (int i = 0; i < 4; i++) {
        int m = m0 + (ty << 2) + i;
        float4 o;
        o.x = acc[i][0] + bv.x;
        o.y = acc[i][1] + bv.y;
        o.z = acc[i][2] + bv.z;
        o.w = acc[i][3] + bv.w;
        *(float4*)(g_xp + (size_t)m * 256 + n0 + (tx << 2)) = o;
    }
}

// ---------------------------------------------------------------------------
// Fused 2-level LTC scan. 8-CTA clusters, 16 clusters, 4 batch / cluster.
//   ranks 0-3: level 0 (neurons rank*64..), ranks 4-7: level 1.
//   Level-1 runs one time-step behind level-0, fed by h0 broadcasts.
//   Credits (remote mbarrier arrives) bound level-0's lead to 2 steps.
// ---------------------------------------------------------------------------
#define CS    8
#define BLKF  264        // floats per 64-neuron block: 4 batch x 64 + 8 pad
#define BLKB  1024       // payload bytes per block (4 x 64 x 4)

typedef unsigned long long u64t;

__device__ __forceinline__ uint32_t smem_u32(const void* p) {
    return (uint32_t)__cvta_generic_to_shared(p);
}
__device__ __forceinline__ u64t pk2(float x, float y) {
    u64t r; asm("mov.b64 %0, {%1,%2};" : "=l"(r) : "f"(x), "f"(y)); return r;
}
__device__ __forceinline__ void fma2(u64t& d, u64t a, u64t b) {
    asm("fma.rn.f32x2 %0, %1, %2, %0;" : "+l"(d) : "l"(a), "l"(b));
}
__device__ __forceinline__ float hsum2(u64t v) {
    float a, b; asm("mov.b64 {%0,%1}, %2;" : "=f"(a), "=f"(b) : "l"(v));
    return a + b;
}
__device__ __forceinline__ float tanh_fast(float x) {
    float y; asm("tanh.approx.f32 %0, %1;" : "=f"(y) : "f"(x)); return y;
}
__device__ __forceinline__ void mbar_init(uint32_t mb, uint32_t cnt) {
    asm volatile("mbarrier.init.shared.b64 [%0], %1;" :: "r"(mb), "r"(cnt) : "memory");
}
__device__ __forceinline__ void mbar_expect(uint32_t mb, uint32_t bytes) {
    asm volatile("mbarrier.arrive.expect_tx.shared.b64 _, [%0], %1;"
                 :: "r"(mb), "r"(bytes) : "memory");
}
__device__ __forceinline__ void mbar_wait(uint32_t mb, uint32_t par) {
    asm volatile(
        "{ .reg .pred p;\n\t"
        "WAIT_%=:\n\t"
        "  mbarrier.try_wait.parity.acquire.cluster.shared::cta.b64 p, [%0], %1, 0x989680;\n\t"
        "  @!p bra WAIT_%=;\n\t"
        "}" :: "r"(mb), "r"(par) : "memory");
}
__device__ __forceinline__ void bulk_cp(uint32_t dst, uint32_t src, uint32_t mb) {
    asm volatile(
        "cp.async.bulk.shared::cluster.shared::cta.mbarrier::complete_tx::bytes "
        "[%0], [%1], 1024, [%2];"
        :: "r"(dst), "r"(src), "r"(mb) : "memory");
}
__device__ __forceinline__ void remote_arrive(uint32_t mb) {
    asm volatile("mbarrier.arrive.shared::cluster.b64 _, [%0];" :: "r"(mb) : "memory");
}

struct __align__(16) Sm {
    float hbuf[3][4][BLKF];   // own-level h exchange (3-rotation)
    float h0in[2][4][BLKF];   // level-1 only: incoming h0 (2 slots + credits)
    u64t  bar_h[2];           // own-level exchange barriers (even/odd step)
    u64t  bar_hin[2];         // level-1: h0 arrival barriers
    u64t  bar_cr[2];          // level-0: credit barriers (count 4)
};

__global__ void __cluster_dims__(CS, 1, 1) __launch_bounds__(256, 1)
ltc_fused(const float* __restrict__ Wr0, const float* __restrict__ M0,
          const float* __restrict__ T0,
          const float* __restrict__ Wr1, const float* __restrict__ M1,
          const float* __restrict__ T1,
          const float* __restrict__ Wi1, const float* __restrict__ B1,
          float* __restrict__ out)
{
    __shared__ Sm S;

    uint32_t rank;
    asm("mov.u32 %0, %%cluster_ctarank;" : "=r"(rank));
    const int  cl    = blockIdx.x / CS;
    const int  bbase = cl * 4;
    const bool isL0  = rank < 4;
    const int  obi   = isL0 ? (int)rank : (int)rank - 4;   // own block index

    const int tid  = threadIdx.x;
    const int lane = tid & 31;
    const int warp = tid >> 5;
    const int jl   = lane & 7;
    const int ks   = lane >> 3;           // k-slice / batch lane 0..3
    const int j    = warp * 8 + jl;       // local neuron 0..63
    const int jf   = obi * 64 + j;        // level-local neuron 0..255

    const uint32_t mbh[2] = { smem_u32(&S.bar_h[0]),   smem_u32(&S.bar_h[1])   };
    const uint32_t mbi[2] = { smem_u32(&S.bar_hin[0]), smem_u32(&S.bar_hin[1]) };
    const uint32_t mbc[2] = { smem_u32(&S.bar_cr[0]),  smem_u32(&S.bar_cr[1])  };

    if (tid == 0) {
        mbar_init(mbh[0], 1); mbar_init(mbh[1], 1);
        mbar_init(mbi[0], 1); mbar_init(mbi[1], 1);
        mbar_init(mbc[0], 4); mbar_init(mbc[1], 4);
        // Pre-arm phase 0 of the tx barriers (steps 0 and 1).
        mbar_expect(mbh[0], 3 * BLKB);
        mbar_expect(mbh[1], 3 * BLKB);
        if (!isL0) {
            mbar_expect(mbi[0], 4 * BLKB);
            mbar_expect(mbi[1], 4 * BLKB);
        }
    }
    // Zero the h float arrays (barriers live after them in the struct).
    for (int e = tid; e < (3 * 4 + 2 * 4) * BLKF; e += 256)
        ((float*)&S)[e] = 0.f;

    // DSMEM rank-address deltas.
    int32_t dsd[CS];
    #pragma unroll
    for (int c = 0; c < CS; c++) {
        uint32_t ra;
        asm("mapa.shared::cluster.u32 %0, %1, %2;" : "=r"(ra) : "r"(mbh[0]), "r"(c));
        dsd[c] = (int32_t)(ra - mbh[0]);
    }

    // Weights: wa = recurrent (masked); wb2 = W_in1 (level-1 only).
    u64t wa[32], wb2[32];
    {
        const float4* wr = (const float4*)((isL0 ? Wr0 : Wr1) + (size_t)jf * HH + ks * 64);
        const float4* mr = (const float4*)((isL0 ? M0  : M1 ) + (size_t)jf * HH + ks * 64);
        #pragma unroll
        for (int ii = 0; ii < 16; ii++) {
            float4 wv = __ldg(wr + ii);
            float4 mv = __ldg(mr + ii);
            wa[2 * ii + 0] = pk2(wv.x * mv.x, wv.y * mv.y);
            wa[2 * ii + 1] = pk2(wv.z * mv.z, wv.w * mv.w);
        }
        if (!isL0) {
            const float4* wi = (const float4*)(Wi1 + (size_t)jf * HH + ks * 64);
            #pragma unroll
            for (int ii = 0; ii < 16; ii++) {
                float4 wv = __ldg(wi + ii);
                wb2[2 * ii + 0] = pk2(wv.x, wv.y);
                wb2[2 * ii + 1] = pk2(wv.z, wv.w);
            }
        } else {
            #pragma unroll
            for (int ii = 0; ii < 32; ii++) wb2[ii] = 0;
        }
    }

    const float tr     = isL0 ? T0[jf] : T1[jf];
    const float invtau = 1.0f / (log1pf(expf(tr)) + 0.1f);
    const float bias1  = isL0 ? 0.f : __ldg(B1 + jf);

    // This lane handles batch element (bbase + ks) for neuron jf.
    const float* xp   = g_xp + (size_t)((bbase + ks) * TT) * HH + jf;
    float*       outp = out + (size_t)((bbase + ks) * TT) * 512 + (isL0 ? 0 : 256) + jf;

    __syncthreads();
    asm volatile("barrier.cluster.arrive.aligned;" ::: "memory");
    asm volatile("barrier.cluster.wait.aligned;"   ::: "memory");

    float xq = isL0 ? __ldg(xp) : 0.f;   // level-0 drive for t=0

    int wbuf = 0, rbuf = 2;

    for (int t = 0; t < TT; t++) {
        const int      sl  = t & 1;
        const uint32_t par = (uint32_t)((t >> 1) & 1);

        if (isL0) {
            // Don't overwrite an h0in slot until all level-1 CTAs consumed it.
            if (tid == 0 && t >= 2) mbar_wait(mbc[sl], par ^ 1);
        } else {
            // Wait for h0(t) from the level-0 CTAs, then immediately re-arm
            // this barrier for step t+2 (before credits release level-0).
            mbar_wait(mbi[sl], par);
            if (tid == 0) mbar_expect(mbi[sl], 4 * BLKB);
        }

        const float* hr = &S.hbuf[rbuf][0][0];
        u64t acc[4][2] = {};
        {
            const ulonglong2* pr[4];
            #pragma unroll
            for (int b = 0; b < 4; b++)
                pr[b] = (const ulonglong2*)(hr + ks * BLKF + b * 64);
            #pragma unroll
            for (int ii = 0; ii < 16; ii++) {
                #pragma unroll
                for (int b = 0; b < 4; b++) {
                    ulonglong2 v = pr[b][ii];
                    fma2(acc[b][0], wa[2 * ii + 0], v.x);
                    fma2(acc[b][1], wa[2 * ii + 1], v.y);
                }
            }
        }
        if (!isL0) {
            const float* h0r = &S.h0in[sl][0][0];
            const ulonglong2* pi[4];
            #pragma unroll
            for (int b = 0; b < 4; b++)
                pi[b] = (const ulonglong2*)(h0r + ks * BLKF + b * 64);
            #pragma unroll
            for (int ii = 0; ii < 16; ii++) {
                #pragma unroll
                for (int b = 0; b < 4; b++) {
                    ulonglong2 v = pi[b][ii];
                    fma2(acc[b][0], wb2[2 * ii + 0], v.x);
                    fma2(acc[b][1], wb2[2 * ii + 1], v.y);
                }
            }
        }

        float s[4];
        #pragma unroll
        for (int b = 0; b < 4; b++) {
            s[b] = hsum2(acc[b][0]) + hsum2(acc[b][1]);
            s[b] += __shfl_xor_sync(0xffffffffu, s[b], 8);
            s[b] += __shfl_xor_sync(0xffffffffu, s[b], 16);
        }
        float sv = (ks == 0) ? s[0] : (ks == 1) ? s[1] : (ks == 2) ? s[2] : s[3];
        sv += isL0 ? xq : bias1;

        float hold = hr[obi * BLKF + ks * 64 + j];
        float hn   = fmaf(tanh_fast(sv) - hold, invtau, hold);

        S.hbuf[wbuf][obi][ks * 64 + j] = hn;
        __syncthreads();

        if (tid == 0) {
            asm volatile("fence.proxy.async.shared::cta;" ::: "memory");
            const uint32_t src = smem_u32(&S.hbuf[wbuf][obi][0]);
            if (isL0) {
                #pragma unroll
                for (int c = 1; c < 4; c++) {
                    const int p = ((int)rank + c) & 3;
                    bulk_cp(src + dsd[p], src, mbh[sl] + dsd[p]);
                }
                const uint32_t dsti = smem_u32(&S.h0in[sl][obi][0]);
                #pragma unroll
                for (int r = 4; r < 8; r++)
                    bulk_cp(dsti + dsd[r], src, mbi[sl] + dsd[r]);
            } else {
                #pragma unroll
                for (int c = 1; c < 4; c++) {
                    const int p = 4 + ((obi + c) & 3);
                    bulk_cp(src + dsd[p], src, mbh[sl] + dsd[p]);
                }
            }
        }
        // Credits: level-1 finished reading h0in[sl] (all reads precede the
        // bar.sync above). One thread per CTA arrives on all 4 level-0 CTAs.
        if (!isL0 && tid == 32) {
            #pragma unroll
            for (int p = 0; p < 4; p++)
                remote_arrive(mbc[sl] + dsd[p]);
        }

        outp[(size_t)t * 512] = hn;
        if (isL0 && t + 1 < TT)
            xq = __ldg(xp + (size_t)(t + 1) * HH);

        // Wait for our own level's exchange of h(t), then re-arm for t+2.
        mbar_wait(mbh[sl], par);
        if (tid == 0) mbar_expect(mbh[sl], 3 * BLKB);

        rbuf = wbuf;
        wbuf = (wbuf == 2) ? 0 : wbuf + 1;
    }

    // Nobody exits while peers' DSMEM traffic may still target us.
    asm volatile("barrier.cluster.arrive.aligned;" ::: "memory");
    asm volatile("barrier.cluster.wait.aligned;"   ::: "memory");
}

// ---------------------------------------------------------------------------
// Launch: gemm(xp0) -> fused 2-level scan
// ---------------------------------------------------------------------------
extern "C" void kernel_launch(void* const* d_in, const int* in_sizes, int n_in,
                              void* d_out, int out_size)
{
    const int*   tokens = (const int*)  d_in[0];
    const float* emb    = (const float*)d_in[1];
    const float* W_in0  = (const float*)d_in[2];
    const float* W_rec0 = (const float*)d_in[3];
    const float* b0     = (const float*)d_in[4];
    const float* tau0   = (const float*)d_in[5];
    const float* mask0  = (const float*)d_in[6];
    const float* W_in1  = (const float*)d_in[7];
    const float* W_rec1 = (const float*)d_in[8];
    const float* b1     = (const float*)d_in[9];
    const float* tau1   = (const float*)d_in[10];
    const float* mask1  = (const float*)d_in[11];
    float* out = (float*)d_out;

    (void)in_sizes; (void)n_in; (void)out_size;

    dim3 ggrid(BT / 64, HH / 64);   // 128 x 4

    // Level-0 input drive (gathers emb rows by token id).
    gemm_xp<<<ggrid, 256>>>(emb, tokens, EE, W_in0, b0);
    // Fused level-0 + level-1 scan: 16 clusters x 8 CTAs.
    ltc_fused<<<128, 256>>>(W_rec0, mask0, tau0,
                            W_rec1, mask1, tau1,
                            W_in1, b1, out);
}

// round 8
// speedup vs baseline: 1.6614x; 1.6614x over previous
#include <cuda_runtime.h>
#include <cstdint>
#include <math.h>

// Problem constants
#define BB   64
#define TT   128
#define EE   256
#define HH   256
#define BT   (BB*TT)        // 8192

// Scratch: input-drive buffer xp[B*T, HH] (8 MB), reused for level 0 then 1.
__device__ float g_xp[BT * HH];

// ---------------------------------------------------------------------------
// GEMM: g_xp[m, n] = sum_k A[row(m), k] * W[n, k] + bias[n]
// ---------------------------------------------------------------------------
__global__ __launch_bounds__(256) void gemm_xp(
    const float* __restrict__ A, const int* __restrict__ rowidx, int astride,
    const float* __restrict__ W, const float* __restrict__ bias)
{
    __shared__ float As[32][68];
    __shared__ float Bs[32][68];

    const int m0  = blockIdx.x * 64;
    const int n0  = blockIdx.y * 64;
    const int tid = threadIdx.x;
    const int lr  = tid >> 3;
    const int lk  = (tid & 7) << 2;
    const int ty  = tid >> 4;
    const int tx  = tid & 15;

    float acc[4][4] = {};

    for (int k0 = 0; k0 < 256; k0 += 32) {
        #pragma unroll
        for (int rr = 0; rr < 2; rr++) {
            int m  = m0 + lr + rr * 32;
            int ar = rowidx ? rowidx[m] : m;
            float4 a4 = *(const float4*)(A + (size_t)ar * astride + k0 + lk);
            As[lk + 0][lr + rr * 32] = a4.x;
            As[lk + 1][lr + rr * 32] = a4.y;
            As[lk + 2][lr + rr * 32] = a4.z;
            As[lk + 3][lr + rr * 32] = a4.w;

            int n = n0 + lr + rr * 32;
            float4 b4 = *(const float4*)(W + (size_t)n * 256 + k0 + lk);
            Bs[lk + 0][lr + rr * 32] = b4.x;
            Bs[lk + 1][lr + rr * 32] = b4.y;
            Bs[lk + 2][lr + rr * 32] = b4.z;
            Bs[lk + 3][lr + rr * 32] = b4.w;
        }
        __syncthreads();

        #pragma unroll
        for (int kk = 0; kk < 32; kk++) {
            float a[4], b[4];
            *(float4*)a = *(const float4*)&As[kk][ty << 2];
            *(float4*)b = *(const float4*)&Bs[kk][tx << 2];
            #pragma unroll
            for (int i = 0; i < 4; i++)
                #pragma unroll
                for (int jx = 0; jx < 4; jx++)
                    acc[i][jx] = fmaf(a[i], b[jx], acc[i][jx]);
        }
        __syncthreads();
    }

    float4 bv = *(const float4*)(bias + n0 + (tx << 2));
    #pragma unroll
    for (int i = 0; i < 4; i++) {
        int m = m0 + (ty << 2) + i;
        float4 o;
        o.x = acc[i][0] + bv.x;
        o.y = acc[i][1] + bv.y;
        o.z = acc[i][2] + bv.z;
        o.w = acc[i][3] + bv.w;
        *(float4*)(g_xp + (size_t)m * 256 + n0 + (tx << 2)) = o;
    }
}

// ---------------------------------------------------------------------------
// LTC scan: 4-CTA clusters, 32 clusters (128 CTAs), 2 batch elems / cluster.
//   - h stored as interleaved (b0,b1) float pairs; rank block = 64 pairs
//     (512 B payload) at stride 132 floats -> ks read groups bank-disjoint.
//   - Weights duplicated per k as (w_k,w_k); fma.rn.f32x2 does both batches.
//   - Transport: producer lanes st.async.b64 their pair to ALL 4 ranks (self
//     included). The tx mbarrier (2048 B/step) is the ONLY sync in the loop:
//     no STS staging, no __syncthreads, no fence, no bulk engine.
//   - Two alternating mbarriers + 3-buffer rotation (as round 4).
// ---------------------------------------------------------------------------
#define CS   4
#define BLK  132     // floats per rank block: 128 data (64 pairs) + 4 pad

typedef unsigned long long u64t;

__device__ __forceinline__ uint32_t smem_u32(const void* p) {
    return (uint32_t)__cvta_generic_to_shared(p);
}
__device__ __forceinline__ u64t pk2(float x, float y) {
    u64t r; asm("mov.b64 %0, {%1,%2};" : "=l"(r) : "f"(x), "f"(y)); return r;
}
__device__ __forceinline__ void fma2(u64t& d, u64t a, u64t b) {
    asm("fma.rn.f32x2 %0, %1, %2, %0;" : "+l"(d) : "l"(a), "l"(b));
}
__device__ __forceinline__ void add2(u64t& d, u64t a) {
    asm("add.rn.f32x2 %0, %0, %1;" : "+l"(d) : "l"(a));
}
__device__ __forceinline__ float tanh_fast(float x) {
    float y; asm("tanh.approx.f32 %0, %1;" : "=f"(y) : "f"(x)); return y;
}
__device__ __forceinline__ void st_async_b64(uint32_t addr, u64t v, uint32_t mb) {
    asm volatile("st.async.shared::cluster.mbarrier::complete_tx::bytes.b64 [%0], %1, [%2];"
                 :: "r"(addr), "l"(v), "r"(mb) : "memory");
}
__device__ __forceinline__ void mbar_wait(uint32_t mb, uint32_t par) {
    asm volatile(
        "{ .reg .pred p;\n\t"
        "WAIT_%=:\n\t"
        "  mbarrier.try_wait.parity.acquire.cluster.shared::cta.b64 p, [%0], %1, 0x989680;\n\t"
        "  @!p bra WAIT_%=;\n\t"
        "}" :: "r"(mb), "r"(par) : "memory");
}

__global__ void __cluster_dims__(CS, 1, 1) __launch_bounds__(256, 1)
ltc_scan(const float* __restrict__ Wrec, const float* __restrict__ mask,
         const float* __restrict__ tau_raw, float* __restrict__ out,
         int outoff)
{
    __shared__ __align__(16) float hb[3][CS][BLK];
    __shared__ u64t mbar[2];

    uint32_t rank;
    asm("mov.u32 %0, %%cluster_ctarank;" : "=r"(rank));
    const int cl = blockIdx.x / CS;
    const int b0 = cl * 2;
    const int b1 = b0 + 1;

    const int tid  = threadIdx.x;
    const int lane = tid & 31;
    const int warp = tid >> 5;
    const int jl   = lane & 7;
    const int ks   = lane >> 3;
    const int j    = warp * 8 + jl;
    const int jf   = (int)rank * 64 + j;

    const uint32_t mb_u32[2] = { smem_u32(&mbar[0]), smem_u32(&mbar[1]) };
    if (tid == 0) {
        asm volatile("mbarrier.init.shared.b64 [%0], 1;" :: "r"(mb_u32[0]) : "memory");
        asm volatile("mbarrier.init.shared.b64 [%0], 1;" :: "r"(mb_u32[1]) : "memory");
        asm volatile("mbarrier.arrive.expect_tx.shared.b64 _, [%0], 2048;"
                     :: "r"(mb_u32[0]) : "memory");
        asm volatile("mbarrier.arrive.expect_tx.shared.b64 _, [%0], 2048;"
                     :: "r"(mb_u32[1]) : "memory");
    }

    for (int e = tid; e < 3 * CS * BLK; e += 256)
        ((float*)hb)[e] = 0.f;

    int32_t dsd[CS];
    #pragma unroll
    for (int c = 0; c < CS; c++) {
        uint32_t ra;
        asm("mapa.shared::cluster.u32 %0, %1, %2;" : "=r"(ra) : "r"(mb_u32[0]), "r"(c));
        dsd[c] = (int32_t)(ra - mb_u32[0]);
    }

    // 64 masked weights (k in [ks*64, ks*64+64)), duplicated (w_k, w_k).
    u64t w2[64];
    {
        const float4* wr = (const float4*)(Wrec + (size_t)jf * HH + ks * 64);
        const float4* mr = (const float4*)(mask + (size_t)jf * HH + ks * 64);
        #pragma unroll
        for (int ii = 0; ii < 16; ii++) {
            float4 wv = __ldg(wr + ii);
            float4 mv = __ldg(mr + ii);
            float w0 = wv.x * mv.x, w1 = wv.y * mv.y;
            float wq = wv.z * mv.z, w3 = wv.w * mv.w;
            w2[4 * ii + 0] = pk2(w0, w0);
            w2[4 * ii + 1] = pk2(w1, w1);
            w2[4 * ii + 2] = pk2(wq, wq);
            w2[4 * ii + 3] = pk2(w3, w3);
        }
    }

    const float tr     = tau_raw[jf];
    const float invtau = 1.0f / (log1pf(expf(tr)) + 0.1f);

    const float* xp0 = g_xp + (size_t)(b0 * TT) * HH + jf;
    const float* xp1 = g_xp + (size_t)(b1 * TT) * HH + jf;
    float* out0 = out + (size_t)(b0 * TT) * 512 + outoff + jf;
    float* out1 = out + (size_t)(b1 * TT) * 512 + outoff + jf;

    __syncthreads();
    asm volatile("barrier.cluster.arrive.aligned;" ::: "memory");
    asm volatile("barrier.cluster.wait.aligned;"   ::: "memory");

    float xq0 = __ldg(xp0);
    float xq1 = __ldg(xp1);

    int wb = 0, rb = 2;

    for (int t = 0; t < TT; t++) {
        const uint32_t mbx = mb_u32[t & 1];

        const u64t hop = *(const u64t*)(&hb[rb][rank][2 * j]);

        const ulonglong2* ph = (const ulonglong2*)(&hb[rb][ks][0]);
        u64t a0 = 0, a1 = 0, a2 = 0, a3 = 0;
        #pragma unroll
        for (int ii = 0; ii < 16; ii++) {
            ulonglong2 v0 = ph[2 * ii + 0];
            ulonglong2 v1 = ph[2 * ii + 1];
            fma2(a0, w2[4 * ii + 0], v0.x);
            fma2(a1, w2[4 * ii + 1], v0.y);
            fma2(a2, w2[4 * ii + 2], v1.x);
            fma2(a3, w2[4 * ii + 3], v1.y);
        }
        add2(a0, a1);
        add2(a2, a3);
        add2(a0, a2);
        {
            u64t tswap = __shfl_xor_sync(0xffffffffu, (unsigned long long)a0, 8);
            add2(a0, tswap);
            tswap = __shfl_xor_sync(0xffffffffu, (unsigned long long)a0, 16);
            add2(a0, tswap);
        }

        float s0, s1, h0o, h1o;
        asm("mov.b64 {%0,%1}, %2;" : "=f"(s0), "=f"(s1) : "l"(a0));
        asm("mov.b64 {%0,%1}, %2;" : "=f"(h0o), "=f"(h1o) : "l"(hop));

        float hn0 = fmaf(tanh_fast(s0 + xq0) - h0o, invtau, h0o);
        float hn1 = fmaf(tanh_fast(s1 + xq1) - h1o, invtau, h1o);

        if (ks == 0) {
            const u64t hv = pk2(hn0, hn1);
            const uint32_t la = smem_u32(&hb[wb][rank][2 * j]);
            #pragma unroll
            for (int c = 0; c < CS; c++)
                st_async_b64(la + dsd[c], hv, mbx + dsd[c]);
        }

        if (ks == 1) out0[(size_t)t * 512] = hn0;
        if (ks == 2) out1[(size_t)t * 512] = hn1;
        if (t + 1 < TT) {
            xq0 = __ldg(xp0 + (size_t)(t + 1) * HH);
            xq1 = __ldg(xp1 + (size_t)(t + 1) * HH);
        }

        mbar_wait(mbx, (uint32_t)((t >> 1) & 1));
        if (tid == 0)
            asm volatile("mbarrier.arrive.expect_tx.shared.b64 _, [%0], 2048;"
                         :: "r"(mbx) : "memory");

        rb = wb;
        wb = (wb == 2) ? 0 : wb + 1;
    }

    asm volatile("barrier.cluster.arrive.aligned;" ::: "memory");
    asm volatile("barrier.cluster.wait.aligned;"   ::: "memory");
}

// ---------------------------------------------------------------------------
// Launch: gemm(xp0) -> scan0 -> gemm(xp1 from h0 in d_out) -> scan1
// ---------------------------------------------------------------------------
extern "C" void kernel_launch(void* const* d_in, const int* in_sizes, int n_in,
                              void* d_out, int out_size)
{
    const int*   tokens = (const int*)  d_in[0];
    const float* emb    = (const float*)d_in[1];
    const float* W_in0  = (const float*)d_in[2];
    const float* W_rec0 = (const float*)d_in[3];
    const float* b0     = (const float*)d_in[4];
    const float* tau0   = (const float*)d_in[5];
    const float* mask0  = (const float*)d_in[6];
    const float* W_in1  = (const float*)d_in[7];
    const float* W_rec1 = (const float*)d_in[8];
    const float* b1     = (const float*)d_in[9];
    const float* tau1   = (const float*)d_in[10];
    const float* mask1  = (const float*)d_in[11];
    float* out = (float*)d_out;

    (void)in_sizes; (void)n_in; (void)out_size;

    dim3 ggrid(BT / 64, HH / 64);   // 128 x 4

    gemm_xp<<<ggrid, 256>>>(emb, tokens, EE, W_in0, b0);
    ltc_scan<<<128, 256>>>(W_rec0, mask0, tau0, out, 0);
    gemm_xp<<<ggrid, 256>>>(out, nullptr, 512, W_in1, b1);
    ltc_scan<<<128, 256>>>(W_rec1, mask1, tau1, out, 256);
}